// round 12
// baseline (speedup 1.0000x reference)
#include <cuda_runtime.h>
#include <cuda_bf16.h>
#include <math.h>
#include <stdint.h>

// Problem constants
#define Bn     8
#define Cn     192
#define HIMG   128
#define WIMG   128
#define HWn    16384
#define HEADSn 8
#define CPHn   24

// ---------------- scratch (device globals; no allocation anywhere) ----------
__device__ __align__(16) float g_tq[(size_t)Bn * Cn * HWn];
__device__ __align__(16) float g_tk[(size_t)Bn * Cn * HWn];
__device__ __align__(16) float g_tv[(size_t)Bn * Cn * HWn];
__device__ __align__(16) float g_q [(size_t)Bn * Cn * HWn];
__device__ __align__(16) float g_k [(size_t)Bn * Cn * HWn];
__device__ __align__(16) float g_v [(size_t)Bn * Cn * HWn];
__device__ float g_gpart[(size_t)64 * 2 * 16 * 576];
__device__ float g_npart[3 * Bn * Cn * 4];
__device__ float g_S  [64 * 2 * 576];
// pre-converted bf16 hi/lo weights: slots 0=wq 1=wk 2=wv, 3..10 = A[b]
__device__ __align__(16) __nv_bfloat16 g_Whi[11 * Cn * Cn];
__device__ __align__(16) __nv_bfloat16 g_Wlo[11 * Cn * Cn];

// ================= warp-level bf16 MMA helpers ==============================
__device__ __forceinline__ void mma16816(float* c, const uint32_t* a, const uint32_t* b) {
    asm volatile(
        "mma.sync.aligned.m16n8k16.row.col.f32.bf16.bf16.f32 "
        "{%0,%1,%2,%3}, {%4,%5,%6,%7}, {%8,%9}, {%0,%1,%2,%3};"
        : "+f"(c[0]), "+f"(c[1]), "+f"(c[2]), "+f"(c[3])
        : "r"(a[0]), "r"(a[1]), "r"(a[2]), "r"(a[3]), "r"(b[0]), "r"(b[1]));
}
__device__ __forceinline__ void ldsm_x4(uint32_t* r, uint32_t addr) {
    asm volatile("ldmatrix.sync.aligned.m8n8.x4.shared.b16 {%0,%1,%2,%3}, [%4];"
        : "=r"(r[0]), "=r"(r[1]), "=r"(r[2]), "=r"(r[3]) : "r"(addr));
}
__device__ __forceinline__ void ldsm_x4_t(uint32_t* r, uint32_t addr) {
    asm volatile("ldmatrix.sync.aligned.m8n8.x4.trans.shared.b16 {%0,%1,%2,%3}, [%4];"
        : "=r"(r[0]), "=r"(r[1]), "=r"(r[2]), "=r"(r[3]) : "r"(addr));
}
__device__ __forceinline__ uint32_t smem_u32(const void* p) {
    uint32_t a;
    asm("{ .reg .u64 t; cvta.to.shared.u64 t, %1; cvt.u32.u64 %0, t; }" : "=r"(a) : "l"(p));
    return a;
}
// hi/lo bf16 split of a float4, packed 2 bf16/u32 ascending
__device__ __forceinline__ void cvt4(float4 v, uint2& h, uint2& l) {
    float x[4] = {v.x, v.y, v.z, v.w};
    unsigned short hb[4], lb[4];
    #pragma unroll
    for (int i = 0; i < 4; i++) {
        __nv_bfloat16 hh = __float2bfloat16(x[i]);
        float hf = __bfloat162float(hh);
        __nv_bfloat16 ll = __float2bfloat16(x[i] - hf);
        hb[i] = __bfloat16_as_ushort(hh);
        lb[i] = __bfloat16_as_ushort(ll);
    }
    h.x = (uint32_t)hb[0] | ((uint32_t)hb[1] << 16);
    h.y = (uint32_t)hb[2] | ((uint32_t)hb[3] << 16);
    l.x = (uint32_t)lb[0] | ((uint32_t)lb[1] << 16);
    l.y = (uint32_t)lb[2] | ((uint32_t)lb[3] << 16);
}

// ---------------- weight pre-conversion (fp32 -> bf16 hi/lo) ----------------
__global__ void __launch_bounds__(256) cvt_weights(
    const float* __restrict__ wq, const float* __restrict__ wk, const float* __restrict__ wv)
{
    const float* src = (blockIdx.x == 0) ? wq : (blockIdx.x == 1) ? wk : wv;
    __nv_bfloat16* dh = g_Whi + (size_t)blockIdx.x * Cn * Cn;
    __nv_bfloat16* dl = g_Wlo + (size_t)blockIdx.x * Cn * Cn;
    for (int idx = threadIdx.x; idx < Cn * Cn / 4; idx += 256) {
        float4 v = reinterpret_cast<const float4*>(src)[idx];
        uint2 h, l;
        cvt4(v, h, l);
        *reinterpret_cast<uint2*>(dh + idx * 4) = h;
        *reinterpret_cast<uint2*>(dl + idx * 4) = l;
    }
}

// ---------------- persistent MMA GEMM -------------------------------------
// mode 0: 3 GEMMs merged (6144 tiles tensor-major), W slots 0-2.
// mode 1: out GEMM (2048 tiles), per-batch W slots 3+b.
// Full M=192, N-tile 64, K-chunk 64 (3 chunks, 4 ksteps each).
// 256 threads = 8 warps (4m x 2n), warp tile 48x32.
// smem: W_hi[192][200]bf16 (76800B) | W_lo (76800B) |
//       B[2 bufs][hi 64x72 | lo 64x72]bf16 (2*18432B).  Total 190464B.
#define AS_LO_OFF 76800
#define BS_OFF    153600
#define BBUF      18432
#define SMEM_MMA  190464

__global__ void __launch_bounds__(256) gemm_mma(
    int mode,
    const float* __restrict__ X0, const float* __restrict__ X1, const float* __restrict__ X2,
    float* __restrict__ Y0, float* __restrict__ Y1, float* __restrict__ Y2,
    const float* __restrict__ bi0, const float* __restrict__ bi1, const float* __restrict__ bi2)
{
    extern __shared__ __align__(1024) char smem[];
    const uint32_t sb = smem_u32(smem);
    const int tid  = threadIdx.x;
    const int wid  = tid >> 5;
    const int lane = tid & 31;
    const int wm   = (wid >> 1) * 48;    // 0,48,96,144
    const int wn   = (wid & 1) * 32;     // 0,32
    const int lr   = lane & 15;
    const int klan = (lane >> 4) << 3;

    const int total = mode ? 2048 : 6144;
    const int bid = blockIdx.x;
    const int q = total / 148, r = total % 148;
    const int tstart = bid * q + (bid < r ? bid : r);
    const int tcount = q + (bid < r ? 1 : 0);

    uint32_t aBase[3];
    #pragma unroll
    for (int f = 0; f < 3; f++)
        aBase[f] = sb + (uint32_t)((wm + f * 16 + lr) * 200 + klan) * 2u;
    uint32_t bBase[2];
    #pragma unroll
    for (int g2 = 0; g2 < 2; g2++)
        bBase[g2] = sb + BS_OFF + (uint32_t)(lr * 72 + wn + g2 * 16 + klan) * 2u;

    const int lqr = lane >> 2;
    const int kq  = (lane & 3) << 1;

    // decode helper values
    auto decode = [&](int tl, int& tensor, int& b_, int& n_) {
        if (mode == 0) { tensor = tl >> 11; int tt = tl & 2047; b_ = tt >> 8; n_ = (tt & 255) << 6; }
        else           { tensor = 0; b_ = tl >> 8; n_ = (tl & 255) << 6; }
    };

    float acc[3][4][4];
    #pragma unroll
    for (int f = 0; f < 3; f++)
        #pragma unroll
        for (int g = 0; g < 4; g++)
            #pragma unroll
            for (int i = 0; i < 4; i++) acc[f][g][i] = 0.0f;

    // X prefetch: chunk = 64k x 64n; thread covers row xr, 16 cols at xc4
    const int xr  = tid >> 2;
    const int xc4 = (tid & 3) << 4;
    float4 px[4];
    {
        int ts, b_, n_;
        decode(tstart, ts, b_, n_);
        const float* Xb = (mode == 0) ? (ts == 0 ? X0 : ts == 1 ? X1 : X2) : X0;
        const float* xp = Xb + (size_t)b_ * Cn * HWn + n_ + (size_t)xr * HWn + xc4;
        #pragma unroll
        for (int i = 0; i < 4; i++)
            px[i] = *reinterpret_cast<const float4*>(xp + i * 4);
    }

    int curW = -1;
    float brow0[3], brow1[3];
    int p = 0;
    int tile = tstart;
    for (int t = 0; t < tcount; t++, tile++) {
        int tensor, b, n0;
        decode(tile, tensor, b, n0);
        float* Yb = ((mode == 0) ? (tensor == 0 ? Y0 : tensor == 1 ? Y1 : Y2) : Y0)
                    + (size_t)b * Cn * HWn + n0;
        const int wslot = mode ? (3 + b) : tensor;

        #pragma unroll 1
        for (int ch = 0; ch < 3; ch++) {
            // store prefetched X chunk as bf16 hi/lo [k][n] into buf p
            {
                char* bs = smem + BS_OFF + p * BBUF;
                const int ro = (xr * 72 + xc4) * 2;
                #pragma unroll
                for (int i = 0; i < 4; i++) {
                    uint2 h, l;
                    cvt4(px[i], h, l);
                    *reinterpret_cast<uint2*>(bs + ro + i * 8)        = h;
                    *reinterpret_cast<uint2*>(bs + 9216 + ro + i * 8) = l;
                }
            }
            __syncthreads();

            // (re)load all 192 W rows when slot changes (<=2x per CTA in mode0)
            if (ch == 0 && wslot != curW) {
                const __nv_bfloat16* wh = g_Whi + (size_t)wslot * Cn * Cn;
                const __nv_bfloat16* wl = g_Wlo + (size_t)wslot * Cn * Cn;
                #pragma unroll
                for (int j = 0; j < 18; j++) {
                    const int ii = tid + j * 256;
                    const int m = ii / 24, oct = (ii % 24) * 8;
                    uint4 hv = *reinterpret_cast<const uint4*>(wh + m * Cn + oct);
                    uint4 lv = *reinterpret_cast<const uint4*>(wl + m * Cn + oct);
                    *reinterpret_cast<uint4*>(smem + (m * 200 + oct) * 2)             = hv;
                    *reinterpret_cast<uint4*>(smem + AS_LO_OFF + (m * 200 + oct) * 2) = lv;
                }
                const float* bias = (mode == 0) ? (tensor == 0 ? bi0 : tensor == 1 ? bi1 : bi2) : bi0;
                #pragma unroll
                for (int f = 0; f < 3; f++) {
                    brow0[f] = __ldg(bias + wm + f * 16 + lqr);
                    brow1[f] = __ldg(bias + wm + f * 16 + lqr + 8);
                }
                curW = wslot;
                __syncthreads();
            }

            // prefetch next chunk (possibly next tile)
            if (t < tcount - 1 || ch < 2) {
                int ntile = tile, nch = ch + 1;
                if (nch == 3) { nch = 0; ntile = tile + 1; }
                int ts, b_, n_;
                decode(ntile, ts, b_, n_);
                const float* Xb = (mode == 0) ? (ts == 0 ? X0 : ts == 1 ? X1 : X2) : X0;
                const float* xp = Xb + (size_t)b_ * Cn * HWn + n_
                                + (size_t)(nch * 64 + xr) * HWn + xc4;
                #pragma unroll
                for (int i = 0; i < 4; i++)
                    px[i] = *reinterpret_cast<const float4*>(xp + i * 4);
            }

            const uint32_t kByte = (uint32_t)(ch * 128);
            const uint32_t pByte = (uint32_t)(p * BBUF);
            #pragma unroll
            for (int s = 0; s < 4; s++) {
                uint32_t ah[3][4], al[3][4];
                #pragma unroll
                for (int f = 0; f < 3; f++) {
                    ldsm_x4(ah[f], aBase[f] + kByte + s * 32);
                    ldsm_x4(al[f], aBase[f] + AS_LO_OFF + kByte + s * 32);
                }
                uint32_t bh[4][2], bl[4][2];
                #pragma unroll
                for (int g2 = 0; g2 < 2; g2++) {
                    uint32_t tr[4];
                    ldsm_x4_t(tr, bBase[g2] + pByte + s * 2304);
                    bh[g2 * 2][0] = tr[0]; bh[g2 * 2][1] = tr[1];
                    bh[g2 * 2 + 1][0] = tr[2]; bh[g2 * 2 + 1][1] = tr[3];
                    ldsm_x4_t(tr, bBase[g2] + pByte + s * 2304 + 9216);
                    bl[g2 * 2][0] = tr[0]; bl[g2 * 2][1] = tr[1];
                    bl[g2 * 2 + 1][0] = tr[2]; bl[g2 * 2 + 1][1] = tr[3];
                }
                #pragma unroll
                for (int g = 0; g < 4; g++)
                    #pragma unroll
                    for (int f = 0; f < 3; f++) {
                        mma16816(acc[f][g], ah[f], bh[g]);
                        mma16816(acc[f][g], ah[f], bl[g]);
                        mma16816(acc[f][g], al[f], bh[g]);
                    }
            }
            p ^= 1;
        }

        // epilogue
        #pragma unroll
        for (int f = 0; f < 3; f++) {
            const int row = wm + f * 16 + lqr;
            #pragma unroll
            for (int g = 0; g < 4; g++) {
                const int col = wn + g * 8 + kq;
                float2 o0, o1;
                o0.x = acc[f][g][0] + brow0[f]; o0.y = acc[f][g][1] + brow0[f];
                o1.x = acc[f][g][2] + brow1[f]; o1.y = acc[f][g][3] + brow1[f];
                *reinterpret_cast<float2*>(Yb + (size_t)row * HWn + col) = o0;
                *reinterpret_cast<float2*>(Yb + (size_t)(row + 8) * HWn + col) = o1;
                acc[f][g][0] = 0.f; acc[f][g][1] = 0.f;
                acc[f][g][2] = 0.f; acc[f][g][3] = 0.f;
            }
        }
    }
}

// ---------------- pure 3x3 depthwise stencil + norm^2 partial ---------------
__global__ void __launch_bounds__(128) dwconv3(
    const float* __restrict__ dwq, const float* __restrict__ dbq,
    const float* __restrict__ dwk, const float* __restrict__ dbk,
    const float* __restrict__ dwv, const float* __restrict__ dbv)
{
    const int yb = blockIdx.x;
    const int c  = blockIdx.y;
    const int tz = blockIdx.z;
    const int tensor = tz >> 3, b = tz & 7;
    const int tid = threadIdx.x;

    const float* in  = (tensor == 0) ? g_tq : (tensor == 1) ? g_tk : g_tv;
    float*       out = (tensor == 0) ? g_q  : (tensor == 1) ? g_k  : g_v;
    const float* dw  = (tensor == 0) ? dwq  : (tensor == 1) ? dwk  : dwv;
    const float* db  = (tensor == 0) ? dbq  : (tensor == 1) ? dbk  : dbv;

    __shared__ __align__(16) float sm[34][136];
    __shared__ float red[4];

    const size_t chbase = ((size_t)b * Cn + c) * HWn;
    const int y0 = yb * 32;

    if (tid < 34) { sm[tid][3] = 0.0f; sm[tid][132] = 0.0f; }

    #pragma unroll
    for (int i = tid; i < 34 * 32; i += 128) {
        const int r  = i >> 5;
        const int c4 = (i & 31) << 2;
        const int gy = y0 - 1 + r;
        float4 v;
        if (gy >= 0 && gy < HIMG)
            v = *reinterpret_cast<const float4*>(in + chbase + (size_t)gy * WIMG + c4);
        else
            v = make_float4(0.f, 0.f, 0.f, 0.f);
        *reinterpret_cast<float4*>(&sm[r][4 + c4]) = v;
    }

    const float w0 = __ldg(dw + c * 9 + 0), w1 = __ldg(dw + c * 9 + 1), w2 = __ldg(dw + c * 9 + 2);
    const float w3 = __ldg(dw + c * 9 + 3), w4 = __ldg(dw + c * 9 + 4), w5 = __ldg(dw + c * 9 + 5);
    const float w6 = __ldg(dw + c * 9 + 6), w7 = __ldg(dw + c * 9 + 7), w8 = __ldg(dw + c * 9 + 8);
    const float bias = __ldg(db + c);
    __syncthreads();

    const int t = tid;
    float a0 = sm[0][t + 3], a1 = sm[0][t + 4], a2 = sm[0][t + 5];
    float b0 = sm[1][t + 3], b1 = sm[1][t + 4], b2 = sm[1][t + 5];
    float nsum = 0.0f;
    #pragma unroll 8
    for (int r = 0; r < 32; r++) {
        const float d0 = sm[r + 2][t + 3], d1 = sm[r + 2][t + 4], d2 = sm[r + 2][t + 5];
        float o = bias;
        o = fmaf(w0, a0, o); o = fmaf(w1, a1, o); o = fmaf(w2, a2, o);
        o = fmaf(w3, b0, o); o = fmaf(w4, b1, o); o = fmaf(w5, b2, o);
        o = fmaf(w6, d0, o); o = fmaf(w7, d1, o); o = fmaf(w8, d2, o);
        out[chbase + (size_t)(y0 + r) * WIMG + t] = o;
        nsum = fmaf(o, o, nsum);
        a0 = b0; a1 = b1; a2 = b2;
        b0 = d0; b1 = d1; b2 = d2;
    }
    #pragma unroll
    for (int off = 16; off; off >>= 1) nsum += __shfl_xor_sync(0xffffffffu, nsum, off);
    if ((tid & 31) == 0) red[tid >> 5] = nsum;
    __syncthreads();
    if (tid == 0)
        g_npart[(((size_t)tensor * Bn + b) * Cn + c) * 4 + yb] = red[0] + red[1] + red[2] + red[3];
}

// ---------------- Gram partials: persistent over 8 chunks of 128 px ---------
// Grid (16 chunk-groups, 64 bh), 128 threads, 38 KB smem.
// Scalar 6x6 inner loop (R10-proven); acc carried across chunks, epilogue 1x.
#define GSTR2 132
__global__ void __launch_bounds__(128) gram_stats()
{
    const int cg = blockIdx.x;      // 0..15 (chunk group of 8)
    const int bh = blockIdx.y;      // 0..63
    const int b = bh >> 3, h = bh & 7;
    const int tid = threadIdx.x;

    extern __shared__ float gsm[];
    float* qs = gsm;
    float* ks = gsm + 24 * GSTR2;
    float* vs = gsm + 48 * GSTR2;

    const int g    = tid >> 6;
    const int t64  = tid & 63;
    const int kseg = t64 >> 4;      // 0..3
    const int t16  = t64 & 15;
    const int ci   = (t16 & 3) * 6;
    const int di   = (t16 >> 2) * 6;
    const float* Aa = g ? ks : qs;

    float acc[6][6];
    #pragma unroll
    for (int i = 0; i < 6; i++)
        #pragma unroll
        for (int j = 0; j < 6; j++) acc[i][j] = 0.0f;

    #pragma unroll 1
    for (int c8 = 0; c8 < 8; c8++) {
        if (c8 > 0) __syncthreads();   // smem reuse guard
        const int n0 = (cg * 8 + c8) * 128;
        for (int i = tid; i < 24 * 32; i += 128) {
            const int row = i >> 5;
            const int c4  = (i & 31) << 2;
            const size_t base = ((size_t)b * Cn + h * CPHn + row) * HWn + n0 + c4;
            const float4 q4 = *reinterpret_cast<const float4*>(g_q + base);
            const float4 k4 = *reinterpret_cast<const float4*>(g_k + base);
            const float4 v4 = *reinterpret_cast<const float4*>(g_v + base);
            *reinterpret_cast<float4*>(qs + row * GSTR2 + c4) = q4;
            *reinterpret_cast<float4*>(ks + row * GSTR2 + c4) = k4;
            *reinterpret_cast<float4*>(vs + row * GSTR2 + c4) = v4;
        }
        __syncthreads();

        #pragma unroll 4
        for (int tk = 0; tk < 32; tk++) {
            const int k = kseg + (tk << 2);
            float a[6], vv[6];
            #pragma unroll
            for (int i = 0; i < 6; i++) a[i]  = Aa[(ci + i) * GSTR2 + k];
            #pragma unroll
            for (int j = 0; j < 6; j++) vv[j] = vs[(di + j) * GSTR2 + k];
            #pragma unroll
            for (int i = 0; i < 6; i++)
                #pragma unroll
                for (int j = 0; j < 6; j++)
                    acc[i][j] = fmaf(a[i], vv[j], acc[i][j]);
        }
    }
    __syncthreads();

    // in-smem kseg reduction (reuses qs/ks region; dead after compute)
    float* red = gsm;
    if (kseg > 0) {
        const int slot = ((g * 3 + (kseg - 1)) * 16 + t16) * 36;
        #pragma unroll
        for (int i = 0; i < 6; i++)
            #pragma unroll
            for (int j = 0; j < 6; j++)
                red[slot + i * 6 + j] = acc[i][j];
    }
    __syncthreads();
    if (kseg == 0) {
        #pragma unroll
        for (int s = 0; s < 3; s++) {
            const int slot = ((g * 3 + s) * 16 + t16) * 36;
            #pragma unroll
            for (int i = 0; i < 6; i++)
                #pragma unroll
                for (int j = 0; j < 6; j++)
                    acc[i][j] += red[slot + i * 6 + j];
        }
        float* dst = g_gpart + (((size_t)bh * 2 + g) * 16 + cg) * 576;
        #pragma unroll
        for (int i = 0; i < 6; i++)
            #pragma unroll
            for (int j = 0; j < 6; j++)
                dst[(ci + i) * 24 + (di + j)] = acc[i][j];
    }
}

// ---------------- reduce Gram partials (deterministic) ----------------------
__global__ void __launch_bounds__(256) reduce_stats()
{
    const int idx = blockIdx.x * 256 + threadIdx.x;
    if (idx < 64 * 2 * 576) {
        const int e = idx % 576;
        const int r = idx / 576;
        float s = 0.0f;
        const float* src = g_gpart + (size_t)r * 16 * 576 + e;
        #pragma unroll
        for (int t = 0; t < 16; t++) s += src[(size_t)t * 576];
        g_S[idx] = s;
    }
}

// ---------------- softmax + attn1@attn2 + W_proj fold -> A[b] bf16 ----------
__global__ void __launch_bounds__(192) attn_fold(
    const float* __restrict__ temp, const float* __restrict__ wp)
{
    const int bh = blockIdx.x;
    const int b = bh >> 3, h = bh & 7;
    const int tidx = threadIdx.x;
    const int lane = tidx & 31;
    __shared__ float a1[24][25], a2[24][25];
    __shared__ float Msh[24][25];
    __shared__ float nrm[3][24];

    if (tidx < 32) {
        if (lane < 24) {
            const int c = h * CPHn + lane;
            #pragma unroll
            for (int tz = 0; tz < 3; tz++) {
                const float* p = g_npart + (((size_t)tz * Bn + b) * Cn + c) * 4;
                nrm[tz][lane] = fmaxf(sqrtf(p[0] + p[1] + p[2] + p[3]), 1e-12f);
            }
        }
        __syncwarp();
        const float tp = temp[h];
        if (lane < 24) {
            const float* S1 = g_S + (bh * 2 + 0) * 576 + lane * 24;
            const float* S2 = g_S + (bh * 2 + 1) * 576 + lane * 24;
            const float iq = tp / nrm[0][lane];
            const float ik = tp / nrm[1][lane];
            float r1[24], r2[24];
            float m1 = -1e30f, m2 = -1e30f;
            #pragma unroll
            for (int d = 0; d < 24; d++) {
                const float iv = 1.0f / nrm[2][d];
                r1[d] = S1[d] * iq * iv;
                r2[d] = S2[d] * ik * iv;
                m1 = fmaxf(m1, r1[d]);
                m2 = fmaxf(m2, r2[d]);
            }
            float s1 = 0.f, s2 = 0.f;
            #pragma unroll
            for (int d = 0; d < 24; d++) {
                r1[d] = expf(r1[d] - m1); s1 += r1[d];
                r2[d] = expf(r2[d] - m2); s2 += r2[d];
            }
            const float i1 = 1.0f / s1, i2 = 1.0f / s2;
            #pragma unroll
            for (int d = 0; d < 24; d++) {
                a1[lane][d] = r1[d] * i1;
                a2[lane][d] = r2[d] * i2;
            }
        }
        __syncwarp();
        if (lane < 24) {
            #pragma unroll
            for (int d = 0; d < 24; d++) {
                float s = 0.f;
                #pragma unroll
                for (int e = 0; e < 24; e++) s = fmaf(a1[lane][e], a2[e][d], s);
                Msh[lane][d] = s / nrm[2][d];
            }
        }
    }
    __syncthreads();

    const int o = tidx;   // 0..191
    const float* wrow = wp + (size_t)o * Cn + h * CPHn;
    float wreg[24];
    #pragma unroll
    for (int c2 = 0; c2 < CPHn; c2++) wreg[c2] = __ldg(wrow + c2);
    const size_t base = (size_t)(3 + b) * Cn * Cn + (size_t)o * Cn + h * CPHn;
    #pragma unroll
    for (int d = 0; d < CPHn; d++) {
        float s = 0.f;
        #pragma unroll
        for (int c2 = 0; c2 < CPHn; c2++) s = fmaf(wreg[c2], Msh[c2][d], s);
        __nv_bfloat16 hi = __float2bfloat16(s);
        __nv_bfloat16 lo = __float2bfloat16(s - __bfloat162float(hi));
        g_Whi[base + d] = hi;
        g_Wlo[base + d] = lo;
    }
}

// ---------------- launch ----------------------------------------------------
extern "C" void kernel_launch(void* const* d_in, const int* in_sizes, int n_in,
                              void* d_out, int out_size)
{
    const float* x    = (const float*)d_in[0];
    const float* edge = (const float*)d_in[1];
    const float* grad = (const float*)d_in[2];
    const float* w_q  = (const float*)d_in[3];  const float* b_q  = (const float*)d_in[4];
    const float* w_k  = (const float*)d_in[5];  const float* b_k  = (const float*)d_in[6];
    const float* w_v  = (const float*)d_in[7];  const float* b_v  = (const float*)d_in[8];
    const float* dw_q = (const float*)d_in[9];  const float* db_q = (const float*)d_in[10];
    const float* dw_k = (const float*)d_in[11]; const float* db_k = (const float*)d_in[12];
    const float* dw_v = (const float*)d_in[13]; const float* db_v = (const float*)d_in[14];
    const float* w_p  = (const float*)d_in[15]; const float* b_p  = (const float*)d_in[16];
    const float* temp = (const float*)d_in[17];
    float* out = (float*)d_out;

    float *tq, *tk, *tv, *vv;
    cudaGetSymbolAddress((void**)&tq,  g_tq);
    cudaGetSymbolAddress((void**)&tk,  g_tk);
    cudaGetSymbolAddress((void**)&tv,  g_tv);
    cudaGetSymbolAddress((void**)&vv,  g_v);

    cudaFuncSetAttribute((const void*)gemm_mma,
                         cudaFuncAttributeMaxDynamicSharedMemorySize, SMEM_MMA);
    const int gsmem = 3 * 24 * GSTR2 * (int)sizeof(float);   // 38016
    cudaFuncSetAttribute((const void*)gram_stats,
                         cudaFuncAttributeMaxDynamicSharedMemorySize, gsmem);

    cvt_weights<<<3, 256>>>(w_q, w_k, w_v);
    // merged q/k/v conv1x1 GEMMs
    gemm_mma<<<148, 256, SMEM_MMA>>>(0, edge, grad, x, tq, tk, tv, b_q, b_k, b_v);
    dwconv3<<<dim3(4, 192, 24), 128>>>(dw_q, db_q, dw_k, db_k, dw_v, db_v);
    gram_stats<<<dim3(16, 64), 128, gsmem>>>();
    reduce_stats<<<288, 256>>>();
    attn_fold<<<64, 192>>>(temp, w_p);
    // final GEMM: out = A[b] @ v + b_proj
    gemm_mma<<<148, 256, SMEM_MMA>>>(1, vv, nullptr, nullptr, out, nullptr, nullptr,
                                     b_p, nullptr, nullptr);
}

// round 13
// speedup vs baseline: 1.1824x; 1.1824x over previous
#include <cuda_runtime.h>
#include <cuda_bf16.h>
#include <math.h>
#include <stdint.h>

// Problem constants
#define Bn     8
#define Cn     192
#define HIMG   128
#define WIMG   128
#define HWn    16384
#define HEADSn 8
#define CPHn   24

// ---------------- scratch (device globals; no allocation anywhere) ----------
__device__ __align__(16) float g_tq[(size_t)Bn * Cn * HWn];
__device__ __align__(16) float g_tk[(size_t)Bn * Cn * HWn];
__device__ __align__(16) float g_tv[(size_t)Bn * Cn * HWn];
__device__ __align__(16) float g_q [(size_t)Bn * Cn * HWn];
__device__ __align__(16) float g_k [(size_t)Bn * Cn * HWn];
__device__ __align__(16) float g_v [(size_t)Bn * Cn * HWn];
__device__ float g_gpart[(size_t)64 * 2 * 128 * 576];
__device__ float g_npart[3 * Bn * Cn * 4];
__device__ float g_S  [64 * 2 * 576];
// pre-converted bf16 hi/lo weights: slots 0=wq 1=wk 2=wv, 3..10 = A[b]
__device__ __align__(16) __nv_bfloat16 g_Whi[11 * Cn * Cn];
__device__ __align__(16) __nv_bfloat16 g_Wlo[11 * Cn * Cn];

// ================= warp-level bf16 MMA helpers ==============================
__device__ __forceinline__ void mma16816(float* c, const uint32_t* a, const uint32_t* b) {
    asm volatile(
        "mma.sync.aligned.m16n8k16.row.col.f32.bf16.bf16.f32 "
        "{%0,%1,%2,%3}, {%4,%5,%6,%7}, {%8,%9}, {%0,%1,%2,%3};"
        : "+f"(c[0]), "+f"(c[1]), "+f"(c[2]), "+f"(c[3])
        : "r"(a[0]), "r"(a[1]), "r"(a[2]), "r"(a[3]), "r"(b[0]), "r"(b[1]));
}
__device__ __forceinline__ void ldsm_x4(uint32_t* r, uint32_t addr) {
    asm volatile("ldmatrix.sync.aligned.m8n8.x4.shared.b16 {%0,%1,%2,%3}, [%4];"
        : "=r"(r[0]), "=r"(r[1]), "=r"(r[2]), "=r"(r[3]) : "r"(addr));
}
__device__ __forceinline__ void ldsm_x4_t(uint32_t* r, uint32_t addr) {
    asm volatile("ldmatrix.sync.aligned.m8n8.x4.trans.shared.b16 {%0,%1,%2,%3}, [%4];"
        : "=r"(r[0]), "=r"(r[1]), "=r"(r[2]), "=r"(r[3]) : "r"(addr));
}
__device__ __forceinline__ uint32_t smem_u32(const void* p) {
    uint32_t a;
    asm("{ .reg .u64 t; cvta.to.shared.u64 t, %1; cvt.u32.u64 %0, t; }" : "=r"(a) : "l"(p));
    return a;
}
__device__ __forceinline__ void cp16(uint32_t saddr, const void* g) {
    asm volatile("cp.async.cg.shared.global [%0], [%1], 16;" :: "r"(saddr), "l"(g) : "memory");
}
#define CP_COMMIT() asm volatile("cp.async.commit_group;" ::: "memory")
#define CP_WAIT0()  asm volatile("cp.async.wait_group 0;" ::: "memory")

// hi/lo bf16 split of a float4, packed 2 bf16/u32 ascending
__device__ __forceinline__ void cvt4(float4 v, uint2& h, uint2& l) {
    float x[4] = {v.x, v.y, v.z, v.w};
    unsigned short hb[4], lb[4];
    #pragma unroll
    for (int i = 0; i < 4; i++) {
        __nv_bfloat16 hh = __float2bfloat16(x[i]);
        float hf = __bfloat162float(hh);
        __nv_bfloat16 ll = __float2bfloat16(x[i] - hf);
        hb[i] = __bfloat16_as_ushort(hh);
        lb[i] = __bfloat16_as_ushort(ll);
    }
    h.x = (uint32_t)hb[0] | ((uint32_t)hb[1] << 16);
    h.y = (uint32_t)hb[2] | ((uint32_t)hb[3] << 16);
    l.x = (uint32_t)lb[0] | ((uint32_t)lb[1] << 16);
    l.y = (uint32_t)lb[2] | ((uint32_t)lb[3] << 16);
}

// ---------------- weight pre-conversion (fp32 -> bf16 hi/lo) ----------------
__global__ void __launch_bounds__(256) cvt_weights(
    const float* __restrict__ wq, const float* __restrict__ wk, const float* __restrict__ wv)
{
    const float* src = (blockIdx.x == 0) ? wq : (blockIdx.x == 1) ? wk : wv;
    __nv_bfloat16* dh = g_Whi + (size_t)blockIdx.x * Cn * Cn;
    __nv_bfloat16* dl = g_Wlo + (size_t)blockIdx.x * Cn * Cn;
    for (int idx = threadIdx.x; idx < Cn * Cn / 4; idx += 256) {
        float4 v = reinterpret_cast<const float4*>(src)[idx];
        uint2 h, l;
        cvt4(v, h, l);
        *reinterpret_cast<uint2*>(dh + idx * 4) = h;
        *reinterpret_cast<uint2*>(dl + idx * 4) = l;
    }
}

// ---------------- persistent MMA GEMM -------------------------------------
// mode 0: 3 GEMMs merged (6144 tiles tensor-major), W slots 0-2.
// mode 1: out GEMM (2048 tiles), per-batch W slots 3+b.
#define AS_LO_OFF 76800
#define BS_OFF    153600
#define BBUF      18432
#define SMEM_MMA  190464

__global__ void __launch_bounds__(256) gemm_mma(
    int mode,
    const float* __restrict__ X0, const float* __restrict__ X1, const float* __restrict__ X2,
    float* __restrict__ Y0, float* __restrict__ Y1, float* __restrict__ Y2,
    const float* __restrict__ bi0, const float* __restrict__ bi1, const float* __restrict__ bi2)
{
    extern __shared__ __align__(1024) char smem[];
    const uint32_t sb = smem_u32(smem);
    const int tid  = threadIdx.x;
    const int wid  = tid >> 5;
    const int lane = tid & 31;
    const int wm   = (wid >> 1) * 48;
    const int wn   = (wid & 1) * 32;
    const int lr   = lane & 15;
    const int klan = (lane >> 4) << 3;

    const int total = mode ? 2048 : 6144;
    const int bid = blockIdx.x;
    const int q = total / 148, r = total % 148;
    const int tstart = bid * q + (bid < r ? bid : r);
    const int tcount = q + (bid < r ? 1 : 0);

    uint32_t aBase[3];
    #pragma unroll
    for (int f = 0; f < 3; f++)
        aBase[f] = sb + (uint32_t)((wm + f * 16 + lr) * 200 + klan) * 2u;
    uint32_t bBase[2];
    #pragma unroll
    for (int g2 = 0; g2 < 2; g2++)
        bBase[g2] = sb + BS_OFF + (uint32_t)(lr * 72 + wn + g2 * 16 + klan) * 2u;

    const int lqr = lane >> 2;
    const int kq  = (lane & 3) << 1;

    auto decode = [&](int tl, int& tensor, int& b_, int& n_) {
        if (mode == 0) { tensor = tl >> 11; int tt = tl & 2047; b_ = tt >> 8; n_ = (tt & 255) << 6; }
        else           { tensor = 0; b_ = tl >> 8; n_ = (tl & 255) << 6; }
    };

    float acc[3][4][4];
    #pragma unroll
    for (int f = 0; f < 3; f++)
        #pragma unroll
        for (int g = 0; g < 4; g++)
            #pragma unroll
            for (int i = 0; i < 4; i++) acc[f][g][i] = 0.0f;

    const int xr  = tid >> 2;
    const int xc4 = (tid & 3) << 4;
    float4 px[4];
    {
        int ts, b_, n_;
        decode(tstart, ts, b_, n_);
        const float* Xb = (mode == 0) ? (ts == 0 ? X0 : ts == 1 ? X1 : X2) : X0;
        const float* xp = Xb + (size_t)b_ * Cn * HWn + n_ + (size_t)xr * HWn + xc4;
        #pragma unroll
        for (int i = 0; i < 4; i++)
            px[i] = *reinterpret_cast<const float4*>(xp + i * 4);
    }

    int curW = -1;
    float brow0[3], brow1[3];
    int p = 0;
    int tile = tstart;
    for (int t = 0; t < tcount; t++, tile++) {
        int tensor, b, n0;
        decode(tile, tensor, b, n0);
        float* Yb = ((mode == 0) ? (tensor == 0 ? Y0 : tensor == 1 ? Y1 : Y2) : Y0)
                    + (size_t)b * Cn * HWn + n0;
        const int wslot = mode ? (3 + b) : tensor;

        #pragma unroll 1
        for (int ch = 0; ch < 3; ch++) {
            {
                char* bs = smem + BS_OFF + p * BBUF;
                const int ro = (xr * 72 + xc4) * 2;
                #pragma unroll
                for (int i = 0; i < 4; i++) {
                    uint2 h, l;
                    cvt4(px[i], h, l);
                    *reinterpret_cast<uint2*>(bs + ro + i * 8)        = h;
                    *reinterpret_cast<uint2*>(bs + 9216 + ro + i * 8) = l;
                }
            }
            __syncthreads();

            if (ch == 0 && wslot != curW) {
                const __nv_bfloat16* wh = g_Whi + (size_t)wslot * Cn * Cn;
                const __nv_bfloat16* wl = g_Wlo + (size_t)wslot * Cn * Cn;
                #pragma unroll
                for (int j = 0; j < 18; j++) {
                    const int ii = tid + j * 256;
                    const int m = ii / 24, oct = (ii % 24) * 8;
                    uint4 hv = *reinterpret_cast<const uint4*>(wh + m * Cn + oct);
                    uint4 lv = *reinterpret_cast<const uint4*>(wl + m * Cn + oct);
                    *reinterpret_cast<uint4*>(smem + (m * 200 + oct) * 2)             = hv;
                    *reinterpret_cast<uint4*>(smem + AS_LO_OFF + (m * 200 + oct) * 2) = lv;
                }
                const float* bias = (mode == 0) ? (tensor == 0 ? bi0 : tensor == 1 ? bi1 : bi2) : bi0;
                #pragma unroll
                for (int f = 0; f < 3; f++) {
                    brow0[f] = __ldg(bias + wm + f * 16 + lqr);
                    brow1[f] = __ldg(bias + wm + f * 16 + lqr + 8);
                }
                curW = wslot;
                __syncthreads();
            }

            if (t < tcount - 1 || ch < 2) {
                int ntile = tile, nch = ch + 1;
                if (nch == 3) { nch = 0; ntile = tile + 1; }
                int ts, b_, n_;
                decode(ntile, ts, b_, n_);
                const float* Xb = (mode == 0) ? (ts == 0 ? X0 : ts == 1 ? X1 : X2) : X0;
                const float* xp = Xb + (size_t)b_ * Cn * HWn + n_
                                + (size_t)(nch * 64 + xr) * HWn + xc4;
                #pragma unroll
                for (int i = 0; i < 4; i++)
                    px[i] = *reinterpret_cast<const float4*>(xp + i * 4);
            }

            const uint32_t kByte = (uint32_t)(ch * 128);
            const uint32_t pByte = (uint32_t)(p * BBUF);
            #pragma unroll
            for (int s = 0; s < 4; s++) {
                uint32_t ah[3][4], al[3][4];
                #pragma unroll
                for (int f = 0; f < 3; f++) {
                    ldsm_x4(ah[f], aBase[f] + kByte + s * 32);
                    ldsm_x4(al[f], aBase[f] + AS_LO_OFF + kByte + s * 32);
                }
                uint32_t bh[4][2], bl[4][2];
                #pragma unroll
                for (int g2 = 0; g2 < 2; g2++) {
                    uint32_t tr[4];
                    ldsm_x4_t(tr, bBase[g2] + pByte + s * 2304);
                    bh[g2 * 2][0] = tr[0]; bh[g2 * 2][1] = tr[1];
                    bh[g2 * 2 + 1][0] = tr[2]; bh[g2 * 2 + 1][1] = tr[3];
                    ldsm_x4_t(tr, bBase[g2] + pByte + s * 2304 + 9216);
                    bl[g2 * 2][0] = tr[0]; bl[g2 * 2][1] = tr[1];
                    bl[g2 * 2 + 1][0] = tr[2]; bl[g2 * 2 + 1][1] = tr[3];
                }
                #pragma unroll
                for (int g = 0; g < 4; g++)
                    #pragma unroll
                    for (int f = 0; f < 3; f++) {
                        mma16816(acc[f][g], ah[f], bh[g]);
                        mma16816(acc[f][g], ah[f], bl[g]);
                        mma16816(acc[f][g], al[f], bh[g]);
                    }
            }
            p ^= 1;
        }

        #pragma unroll
        for (int f = 0; f < 3; f++) {
            const int row = wm + f * 16 + lqr;
            #pragma unroll
            for (int g = 0; g < 4; g++) {
                const int col = wn + g * 8 + kq;
                float2 o0, o1;
                o0.x = acc[f][g][0] + brow0[f]; o0.y = acc[f][g][1] + brow0[f];
                o1.x = acc[f][g][2] + brow1[f]; o1.y = acc[f][g][3] + brow1[f];
                *reinterpret_cast<float2*>(Yb + (size_t)row * HWn + col) = o0;
                *reinterpret_cast<float2*>(Yb + (size_t)(row + 8) * HWn + col) = o1;
                acc[f][g][0] = 0.f; acc[f][g][1] = 0.f;
                acc[f][g][2] = 0.f; acc[f][g][3] = 0.f;
            }
        }
    }
}

// ---------------- pure 3x3 depthwise stencil + norm^2 partial ---------------
__global__ void __launch_bounds__(128) dwconv3(
    const float* __restrict__ dwq, const float* __restrict__ dbq,
    const float* __restrict__ dwk, const float* __restrict__ dbk,
    const float* __restrict__ dwv, const float* __restrict__ dbv)
{
    const int yb = blockIdx.x;
    const int c  = blockIdx.y;
    const int tz = blockIdx.z;
    const int tensor = tz >> 3, b = tz & 7;
    const int tid = threadIdx.x;

    const float* in  = (tensor == 0) ? g_tq : (tensor == 1) ? g_tk : g_tv;
    float*       out = (tensor == 0) ? g_q  : (tensor == 1) ? g_k  : g_v;
    const float* dw  = (tensor == 0) ? dwq  : (tensor == 1) ? dwk  : dwv;
    const float* db  = (tensor == 0) ? dbq  : (tensor == 1) ? dbk  : dbv;

    __shared__ __align__(16) float sm[34][136];
    __shared__ float red[4];

    const size_t chbase = ((size_t)b * Cn + c) * HWn;
    const int y0 = yb * 32;

    if (tid < 34) { sm[tid][3] = 0.0f; sm[tid][132] = 0.0f; }

    #pragma unroll
    for (int i = tid; i < 34 * 32; i += 128) {
        const int r  = i >> 5;
        const int c4 = (i & 31) << 2;
        const int gy = y0 - 1 + r;
        float4 v;
        if (gy >= 0 && gy < HIMG)
            v = *reinterpret_cast<const float4*>(in + chbase + (size_t)gy * WIMG + c4);
        else
            v = make_float4(0.f, 0.f, 0.f, 0.f);
        *reinterpret_cast<float4*>(&sm[r][4 + c4]) = v;
    }

    const float w0 = __ldg(dw + c * 9 + 0), w1 = __ldg(dw + c * 9 + 1), w2 = __ldg(dw + c * 9 + 2);
    const float w3 = __ldg(dw + c * 9 + 3), w4 = __ldg(dw + c * 9 + 4), w5 = __ldg(dw + c * 9 + 5);
    const float w6 = __ldg(dw + c * 9 + 6), w7 = __ldg(dw + c * 9 + 7), w8 = __ldg(dw + c * 9 + 8);
    const float bias = __ldg(db + c);
    __syncthreads();

    const int t = tid;
    float a0 = sm[0][t + 3], a1 = sm[0][t + 4], a2 = sm[0][t + 5];
    float b0 = sm[1][t + 3], b1 = sm[1][t + 4], b2 = sm[1][t + 5];
    float nsum = 0.0f;
    #pragma unroll 8
    for (int r = 0; r < 32; r++) {
        const float d0 = sm[r + 2][t + 3], d1 = sm[r + 2][t + 4], d2 = sm[r + 2][t + 5];
        float o = bias;
        o = fmaf(w0, a0, o); o = fmaf(w1, a1, o); o = fmaf(w2, a2, o);
        o = fmaf(w3, b0, o); o = fmaf(w4, b1, o); o = fmaf(w5, b2, o);
        o = fmaf(w6, d0, o); o = fmaf(w7, d1, o); o = fmaf(w8, d2, o);
        out[chbase + (size_t)(y0 + r) * WIMG + t] = o;
        nsum = fmaf(o, o, nsum);
        a0 = b0; a1 = b1; a2 = b2;
        b0 = d0; b1 = d1; b2 = d2;
    }
    #pragma unroll
    for (int off = 16; off; off >>= 1) nsum += __shfl_xor_sync(0xffffffffu, nsum, off);
    if ((tid & 31) == 0) red[tid >> 5] = nsum;
    __syncthreads();
    if (tid == 0)
        g_npart[(((size_t)tensor * Bn + b) * Cn + c) * 4 + yb] = red[0] + red[1] + red[2] + red[3];
}

// ---------------- Gram partials: 128-px chunks, 6x6 tiles, cp.async loads ---
// Grid (128 chunks, 64 bh), 128 threads, 38 KB smem, 6 CTAs/SM. (R10 layout)
#define GSTR2 132
__global__ void __launch_bounds__(128) gram_stats()
{
    const int chunk = blockIdx.x;   // 0..127
    const int bh    = blockIdx.y;   // 0..63
    const int b = bh >> 3, h = bh & 7;
    const int tid = threadIdx.x;

    extern __shared__ float gsm[];
    float* qs = gsm;
    float* ks = gsm + 24 * GSTR2;
    float* vs = gsm + 48 * GSTR2;
    const uint32_t sq = smem_u32(qs);
    const uint32_t sk = smem_u32(ks);
    const uint32_t sv = smem_u32(vs);

    const int n0 = chunk * 128;
    for (int i = tid; i < 24 * 32; i += 128) {
        const int row = i >> 5;
        const int c4  = (i & 31) << 2;
        const size_t base = ((size_t)b * Cn + h * CPHn + row) * HWn + n0 + c4;
        const uint32_t off = (uint32_t)(row * GSTR2 + c4) * 4u;
        cp16(sq + off, g_q + base);
        cp16(sk + off, g_k + base);
        cp16(sv + off, g_v + base);
    }
    CP_COMMIT();
    CP_WAIT0();
    __syncthreads();

    const int g    = tid >> 6;
    const int t64  = tid & 63;
    const int kseg = t64 >> 4;      // 0..3
    const int t16  = t64 & 15;
    const int ci   = (t16 & 3) * 6;
    const int di   = (t16 >> 2) * 6;
    const float* Aa = g ? ks : qs;

    float acc[6][6];
    #pragma unroll
    for (int i = 0; i < 6; i++)
        #pragma unroll
        for (int j = 0; j < 6; j++) acc[i][j] = 0.0f;

    #pragma unroll 4
    for (int tk = 0; tk < 32; tk++) {
        const int k = kseg + (tk << 2);
        float a[6], vv[6];
        #pragma unroll
        for (int i = 0; i < 6; i++) a[i]  = Aa[(ci + i) * GSTR2 + k];
        #pragma unroll
        for (int j = 0; j < 6; j++) vv[j] = vs[(di + j) * GSTR2 + k];
        #pragma unroll
        for (int i = 0; i < 6; i++)
            #pragma unroll
            for (int j = 0; j < 6; j++)
                acc[i][j] = fmaf(a[i], vv[j], acc[i][j]);
    }
    __syncthreads();

    // in-smem kseg reduction (reuses qs/ks region; dead after compute)
    float* red = gsm;
    if (kseg > 0) {
        const int slot = ((g * 3 + (kseg - 1)) * 16 + t16) * 36;
        #pragma unroll
        for (int i = 0; i < 6; i++)
            #pragma unroll
            for (int j = 0; j < 6; j++)
                red[slot + i * 6 + j] = acc[i][j];
    }
    __syncthreads();
    if (kseg == 0) {
        #pragma unroll
        for (int s = 0; s < 3; s++) {
            const int slot = ((g * 3 + s) * 16 + t16) * 36;
            #pragma unroll
            for (int i = 0; i < 6; i++)
                #pragma unroll
                for (int j = 0; j < 6; j++)
                    acc[i][j] += red[slot + i * 6 + j];
        }
        float* dst = g_gpart + (((size_t)bh * 2 + g) * 128 + chunk) * 576;
        #pragma unroll
        for (int i = 0; i < 6; i++)
            #pragma unroll
            for (int j = 0; j < 6; j++)
                dst[(ci + i) * 24 + (di + j)] = acc[i][j];
    }
}

// ---------------- reduce Gram partials (deterministic) ----------------------
__global__ void __launch_bounds__(256) reduce_stats()
{
    const int idx = blockIdx.x * 256 + threadIdx.x;
    if (idx < 64 * 2 * 576) {
        const int e = idx % 576;
        const int r = idx / 576;
        float s = 0.0f;
        const float* src = g_gpart + (size_t)r * 128 * 576 + e;
        #pragma unroll 8
        for (int t = 0; t < 128; t++) s += src[(size_t)t * 576];
        g_S[idx] = s;
    }
}

// ---------------- softmax + attn1@attn2 + W_proj fold -> A[b] bf16 ----------
__global__ void __launch_bounds__(192) attn_fold(
    const float* __restrict__ temp, const float* __restrict__ wp)
{
    const int bh = blockIdx.x;
    const int b = bh >> 3, h = bh & 7;
    const int tidx = threadIdx.x;
    const int lane = tidx & 31;
    __shared__ float a1[24][25], a2[24][25];
    __shared__ float Msh[24][25];
    __shared__ float nrm[3][24];

    if (tidx < 32) {
        if (lane < 24) {
            const int c = h * CPHn + lane;
            #pragma unroll
            for (int tz = 0; tz < 3; tz++) {
                const float* p = g_npart + (((size_t)tz * Bn + b) * Cn + c) * 4;
                nrm[tz][lane] = fmaxf(sqrtf(p[0] + p[1] + p[2] + p[3]), 1e-12f);
            }
        }
        __syncwarp();
        const float tp = temp[h];
        if (lane < 24) {
            const float* S1 = g_S + (bh * 2 + 0) * 576 + lane * 24;
            const float* S2 = g_S + (bh * 2 + 1) * 576 + lane * 24;
            const float iq = tp / nrm[0][lane];
            const float ik = tp / nrm[1][lane];
            float r1[24], r2[24];
            float m1 = -1e30f, m2 = -1e30f;
            #pragma unroll
            for (int d = 0; d < 24; d++) {
                const float iv = 1.0f / nrm[2][d];
                r1[d] = S1[d] * iq * iv;
                r2[d] = S2[d] * ik * iv;
                m1 = fmaxf(m1, r1[d]);
                m2 = fmaxf(m2, r2[d]);
            }
            float s1 = 0.f, s2 = 0.f;
            #pragma unroll
            for (int d = 0; d < 24; d++) {
                r1[d] = expf(r1[d] - m1); s1 += r1[d];
                r2[d] = expf(r2[d] - m2); s2 += r2[d];
            }
            const float i1 = 1.0f / s1, i2 = 1.0f / s2;
            #pragma unroll
            for (int d = 0; d < 24; d++) {
                a1[lane][d] = r1[d] * i1;
                a2[lane][d] = r2[d] * i2;
            }
        }
        __syncwarp();
        if (lane < 24) {
            #pragma unroll
            for (int d = 0; d < 24; d++) {
                float s = 0.f;
                #pragma unroll
                for (int e = 0; e < 24; e++) s = fmaf(a1[lane][e], a2[e][d], s);
                Msh[lane][d] = s / nrm[2][d];
            }
        }
    }
    __syncthreads();

    const int o = tidx;   // 0..191
    const float* wrow = wp + (size_t)o * Cn + h * CPHn;
    float wreg[24];
    #pragma unroll
    for (int c2 = 0; c2 < CPHn; c2++) wreg[c2] = __ldg(wrow + c2);
    const size_t base = (size_t)(3 + b) * Cn * Cn + (size_t)o * Cn + h * CPHn;
    #pragma unroll
    for (int d = 0; d < CPHn; d++) {
        float s = 0.f;
        #pragma unroll
        for (int c2 = 0; c2 < CPHn; c2++) s = fmaf(wreg[c2], Msh[c2][d], s);
        __nv_bfloat16 hi = __float2bfloat16(s);
        __nv_bfloat16 lo = __float2bfloat16(s - __bfloat162float(hi));
        g_Whi[base + d] = hi;
        g_Wlo[base + d] = lo;
    }
}

// ---------------- launch ----------------------------------------------------
extern "C" void kernel_launch(void* const* d_in, const int* in_sizes, int n_in,
                              void* d_out, int out_size)
{
    const float* x    = (const float*)d_in[0];
    const float* edge = (const float*)d_in[1];
    const float* grad = (const float*)d_in[2];
    const float* w_q  = (const float*)d_in[3];  const float* b_q  = (const float*)d_in[4];
    const float* w_k  = (const float*)d_in[5];  const float* b_k  = (const float*)d_in[6];
    const float* w_v  = (const float*)d_in[7];  const float* b_v  = (const float*)d_in[8];
    const float* dw_q = (const float*)d_in[9];  const float* db_q = (const float*)d_in[10];
    const float* dw_k = (const float*)d_in[11]; const float* db_k = (const float*)d_in[12];
    const float* dw_v = (const float*)d_in[13]; const float* db_v = (const float*)d_in[14];
    const float* w_p  = (const float*)d_in[15]; const float* b_p  = (const float*)d_in[16];
    const float* temp = (const float*)d_in[17];
    float* out = (float*)d_out;

    float *tq, *tk, *tv, *vv;
    cudaGetSymbolAddress((void**)&tq,  g_tq);
    cudaGetSymbolAddress((void**)&tk,  g_tk);
    cudaGetSymbolAddress((void**)&tv,  g_tv);
    cudaGetSymbolAddress((void**)&vv,  g_v);

    cudaFuncSetAttribute((const void*)gemm_mma,
                         cudaFuncAttributeMaxDynamicSharedMemorySize, SMEM_MMA);
    const int gsmem = 3 * 24 * GSTR2 * (int)sizeof(float);   // 38016
    cudaFuncSetAttribute((const void*)gram_stats,
                         cudaFuncAttributeMaxDynamicSharedMemorySize, gsmem);

    cvt_weights<<<3, 256>>>(w_q, w_k, w_v);
    // merged q/k/v conv1x1 GEMMs
    gemm_mma<<<148, 256, SMEM_MMA>>>(0, edge, grad, x, tq, tk, tv, b_q, b_k, b_v);
    dwconv3<<<dim3(4, 192, 24), 128>>>(dw_q, db_q, dw_k, db_k, dw_v, db_v);
    gram_stats<<<dim3(128, 64), 128, gsmem>>>();
    reduce_stats<<<288, 256>>>();
    attn_fold<<<64, 192>>>(temp, w_p);
    // final GEMM: out = A[b] @ v + b_proj
    gemm_mma<<<148, 256, SMEM_MMA>>>(1, vv, nullptr, nullptr, out, nullptr, nullptr,
                                     b_p, nullptr, nullptr);
}

// round 14
// speedup vs baseline: 1.2129x; 1.0258x over previous
#include <cuda_runtime.h>
#include <cuda_bf16.h>
#include <math.h>
#include <stdint.h>

// Problem constants
#define Bn     8
#define Cn     192
#define HIMG   128
#define WIMG   128
#define HWn    16384
#define HEADSn 8
#define CPHn   24

// ---------------- scratch (device globals; no allocation anywhere) ----------
__device__ __align__(16) float g_tq[(size_t)Bn * Cn * HWn];
__device__ __align__(16) float g_tk[(size_t)Bn * Cn * HWn];
__device__ __align__(16) float g_tv[(size_t)Bn * Cn * HWn];
__device__ __align__(16) float g_q [(size_t)Bn * Cn * HWn];
__device__ __align__(16) float g_k [(size_t)Bn * Cn * HWn];
__device__ __align__(16) float g_v [(size_t)Bn * Cn * HWn];
__device__ float g_gpart[(size_t)64 * 2 * 128 * 576];
__device__ float g_npart[3 * Bn * Cn * 2];
__device__ float g_S  [64 * 2 * 576];
// pre-converted bf16 hi/lo weights: slots 0=wq 1=wk 2=wv, 3..10 = A[b]
__device__ __align__(16) __nv_bfloat16 g_Whi[11 * Cn * Cn];
__device__ __align__(16) __nv_bfloat16 g_Wlo[11 * Cn * Cn];

// ================= warp-level bf16 MMA helpers ==============================
__device__ __forceinline__ void mma16816(float* c, const uint32_t* a, const uint32_t* b) {
    asm volatile(
        "mma.sync.aligned.m16n8k16.row.col.f32.bf16.bf16.f32 "
        "{%0,%1,%2,%3}, {%4,%5,%6,%7}, {%8,%9}, {%0,%1,%2,%3};"
        : "+f"(c[0]), "+f"(c[1]), "+f"(c[2]), "+f"(c[3])
        : "r"(a[0]), "r"(a[1]), "r"(a[2]), "r"(a[3]), "r"(b[0]), "r"(b[1]));
}
__device__ __forceinline__ void ldsm_x4(uint32_t* r, uint32_t addr) {
    asm volatile("ldmatrix.sync.aligned.m8n8.x4.shared.b16 {%0,%1,%2,%3}, [%4];"
        : "=r"(r[0]), "=r"(r[1]), "=r"(r[2]), "=r"(r[3]) : "r"(addr));
}
__device__ __forceinline__ void ldsm_x4_t(uint32_t* r, uint32_t addr) {
    asm volatile("ldmatrix.sync.aligned.m8n8.x4.trans.shared.b16 {%0,%1,%2,%3}, [%4];"
        : "=r"(r[0]), "=r"(r[1]), "=r"(r[2]), "=r"(r[3]) : "r"(addr));
}
__device__ __forceinline__ uint32_t smem_u32(const void* p) {
    uint32_t a;
    asm("{ .reg .u64 t; cvta.to.shared.u64 t, %1; cvt.u32.u64 %0, t; }" : "=r"(a) : "l"(p));
    return a;
}
__device__ __forceinline__ void cp16(uint32_t saddr, const void* g) {
    asm volatile("cp.async.cg.shared.global [%0], [%1], 16;" :: "r"(saddr), "l"(g) : "memory");
}
#define CP_COMMIT() asm volatile("cp.async.commit_group;" ::: "memory")
#define CP_WAIT0()  asm volatile("cp.async.wait_group 0;" ::: "memory")

// hi/lo bf16 split of a float4, packed 2 bf16/u32 ascending
__device__ __forceinline__ void cvt4(float4 v, uint2& h, uint2& l) {
    float x[4] = {v.x, v.y, v.z, v.w};
    unsigned short hb[4], lb[4];
    #pragma unroll
    for (int i = 0; i < 4; i++) {
        __nv_bfloat16 hh = __float2bfloat16(x[i]);
        float hf = __bfloat162float(hh);
        __nv_bfloat16 ll = __float2bfloat16(x[i] - hf);
        hb[i] = __bfloat16_as_ushort(hh);
        lb[i] = __bfloat16_as_ushort(ll);
    }
    h.x = (uint32_t)hb[0] | ((uint32_t)hb[1] << 16);
    h.y = (uint32_t)hb[2] | ((uint32_t)hb[3] << 16);
    l.x = (uint32_t)lb[0] | ((uint32_t)lb[1] << 16);
    l.y = (uint32_t)lb[2] | ((uint32_t)lb[3] << 16);
}

// ---------------- weight pre-conversion (fp32 -> bf16 hi/lo) ----------------
__global__ void __launch_bounds__(256) cvt_weights(
    const float* __restrict__ wq, const float* __restrict__ wk, const float* __restrict__ wv)
{
    const float* src = (blockIdx.x == 0) ? wq : (blockIdx.x == 1) ? wk : wv;
    __nv_bfloat16* dh = g_Whi + (size_t)blockIdx.x * Cn * Cn;
    __nv_bfloat16* dl = g_Wlo + (size_t)blockIdx.x * Cn * Cn;
    for (int idx = threadIdx.x; idx < Cn * Cn / 4; idx += 256) {
        float4 v = reinterpret_cast<const float4*>(src)[idx];
        uint2 h, l;
        cvt4(v, h, l);
        *reinterpret_cast<uint2*>(dh + idx * 4) = h;
        *reinterpret_cast<uint2*>(dl + idx * 4) = l;
    }
}

// ---------------- persistent MMA GEMM -------------------------------------
// mode 0: 3 GEMMs merged (6144 tiles tensor-major), W slots 0-2.
// mode 1: out GEMM (2048 tiles), per-batch W slots 3+b.
#define AS_LO_OFF 76800
#define BS_OFF    153600
#define BBUF      18432
#define SMEM_MMA  190464

__global__ void __launch_bounds__(256) gemm_mma(
    int mode,
    const float* __restrict__ X0, const float* __restrict__ X1, const float* __restrict__ X2,
    float* __restrict__ Y0, float* __restrict__ Y1, float* __restrict__ Y2,
    const float* __restrict__ bi0, const float* __restrict__ bi1, const float* __restrict__ bi2)
{
    extern __shared__ __align__(1024) char smem[];
    const uint32_t sb = smem_u32(smem);
    const int tid  = threadIdx.x;
    const int wid  = tid >> 5;
    const int lane = tid & 31;
    const int wm   = (wid >> 1) * 48;
    const int wn   = (wid & 1) * 32;
    const int lr   = lane & 15;
    const int klan = (lane >> 4) << 3;

    const int total = mode ? 2048 : 6144;
    const int bid = blockIdx.x;
    const int q = total / 148, r = total % 148;
    const int tstart = bid * q + (bid < r ? bid : r);
    const int tcount = q + (bid < r ? 1 : 0);

    uint32_t aBase[3];
    #pragma unroll
    for (int f = 0; f < 3; f++)
        aBase[f] = sb + (uint32_t)((wm + f * 16 + lr) * 200 + klan) * 2u;
    uint32_t bBase[2];
    #pragma unroll
    for (int g2 = 0; g2 < 2; g2++)
        bBase[g2] = sb + BS_OFF + (uint32_t)(lr * 72 + wn + g2 * 16 + klan) * 2u;

    const int lqr = lane >> 2;
    const int kq  = (lane & 3) << 1;

    auto decode = [&](int tl, int& tensor, int& b_, int& n_) {
        if (mode == 0) { tensor = tl >> 11; int tt = tl & 2047; b_ = tt >> 8; n_ = (tt & 255) << 6; }
        else           { tensor = 0; b_ = tl >> 8; n_ = (tl & 255) << 6; }
    };

    float acc[3][4][4];
    #pragma unroll
    for (int f = 0; f < 3; f++)
        #pragma unroll
        for (int g = 0; g < 4; g++)
            #pragma unroll
            for (int i = 0; i < 4; i++) acc[f][g][i] = 0.0f;

    const int xr  = tid >> 2;
    const int xc4 = (tid & 3) << 4;
    float4 px[4];
    {
        int ts, b_, n_;
        decode(tstart, ts, b_, n_);
        const float* Xb = (mode == 0) ? (ts == 0 ? X0 : ts == 1 ? X1 : X2) : X0;
        const float* xp = Xb + (size_t)b_ * Cn * HWn + n_ + (size_t)xr * HWn + xc4;
        #pragma unroll
        for (int i = 0; i < 4; i++)
            px[i] = *reinterpret_cast<const float4*>(xp + i * 4);
    }

    int curW = -1;
    float brow0[3], brow1[3];
    int p = 0;
    int tile = tstart;
    for (int t = 0; t < tcount; t++, tile++) {
        int tensor, b, n0;
        decode(tile, tensor, b, n0);
        float* Yb = ((mode == 0) ? (tensor == 0 ? Y0 : tensor == 1 ? Y1 : Y2) : Y0)
                    + (size_t)b * Cn * HWn + n0;
        const int wslot = mode ? (3 + b) : tensor;

        #pragma unroll 1
        for (int ch = 0; ch < 3; ch++) {
            {
                char* bs = smem + BS_OFF + p * BBUF;
                const int ro = (xr * 72 + xc4) * 2;
                #pragma unroll
                for (int i = 0; i < 4; i++) {
                    uint2 h, l;
                    cvt4(px[i], h, l);
                    *reinterpret_cast<uint2*>(bs + ro + i * 8)        = h;
                    *reinterpret_cast<uint2*>(bs + 9216 + ro + i * 8) = l;
                }
            }
            __syncthreads();

            if (ch == 0 && wslot != curW) {
                const __nv_bfloat16* wh = g_Whi + (size_t)wslot * Cn * Cn;
                const __nv_bfloat16* wl = g_Wlo + (size_t)wslot * Cn * Cn;
                #pragma unroll
                for (int j = 0; j < 18; j++) {
                    const int ii = tid + j * 256;
                    const int m = ii / 24, oct = (ii % 24) * 8;
                    uint4 hv = *reinterpret_cast<const uint4*>(wh + m * Cn + oct);
                    uint4 lv = *reinterpret_cast<const uint4*>(wl + m * Cn + oct);
                    *reinterpret_cast<uint4*>(smem + (m * 200 + oct) * 2)             = hv;
                    *reinterpret_cast<uint4*>(smem + AS_LO_OFF + (m * 200 + oct) * 2) = lv;
                }
                const float* bias = (mode == 0) ? (tensor == 0 ? bi0 : tensor == 1 ? bi1 : bi2) : bi0;
                #pragma unroll
                for (int f = 0; f < 3; f++) {
                    brow0[f] = __ldg(bias + wm + f * 16 + lqr);
                    brow1[f] = __ldg(bias + wm + f * 16 + lqr + 8);
                }
                curW = wslot;
                __syncthreads();
            }

            if (t < tcount - 1 || ch < 2) {
                int ntile = tile, nch = ch + 1;
                if (nch == 3) { nch = 0; ntile = tile + 1; }
                int ts, b_, n_;
                decode(ntile, ts, b_, n_);
                const float* Xb = (mode == 0) ? (ts == 0 ? X0 : ts == 1 ? X1 : X2) : X0;
                const float* xp = Xb + (size_t)b_ * Cn * HWn + n_
                                + (size_t)(nch * 64 + xr) * HWn + xc4;
                #pragma unroll
                for (int i = 0; i < 4; i++)
                    px[i] = *reinterpret_cast<const float4*>(xp + i * 4);
            }

            const uint32_t kByte = (uint32_t)(ch * 128);
            const uint32_t pByte = (uint32_t)(p * BBUF);
            #pragma unroll
            for (int s = 0; s < 4; s++) {
                uint32_t ah[3][4], al[3][4];
                #pragma unroll
                for (int f = 0; f < 3; f++) {
                    ldsm_x4(ah[f], aBase[f] + kByte + s * 32);
                    ldsm_x4(al[f], aBase[f] + AS_LO_OFF + kByte + s * 32);
                }
                uint32_t bh[4][2], bl[4][2];
                #pragma unroll
                for (int g2 = 0; g2 < 2; g2++) {
                    uint32_t tr[4];
                    ldsm_x4_t(tr, bBase[g2] + pByte + s * 2304);
                    bh[g2 * 2][0] = tr[0]; bh[g2 * 2][1] = tr[1];
                    bh[g2 * 2 + 1][0] = tr[2]; bh[g2 * 2 + 1][1] = tr[3];
                    ldsm_x4_t(tr, bBase[g2] + pByte + s * 2304 + 9216);
                    bl[g2 * 2][0] = tr[0]; bl[g2 * 2][1] = tr[1];
                    bl[g2 * 2 + 1][0] = tr[2]; bl[g2 * 2 + 1][1] = tr[3];
                }
                #pragma unroll
                for (int g = 0; g < 4; g++)
                    #pragma unroll
                    for (int f = 0; f < 3; f++) {
                        mma16816(acc[f][g], ah[f], bh[g]);
                        mma16816(acc[f][g], ah[f], bl[g]);
                        mma16816(acc[f][g], al[f], bh[g]);
                    }
            }
            p ^= 1;
        }

        #pragma unroll
        for (int f = 0; f < 3; f++) {
            const int row = wm + f * 16 + lqr;
            #pragma unroll
            for (int g = 0; g < 4; g++) {
                const int col = wn + g * 8 + kq;
                float2 o0, o1;
                o0.x = acc[f][g][0] + brow0[f]; o0.y = acc[f][g][1] + brow0[f];
                o1.x = acc[f][g][2] + brow1[f]; o1.y = acc[f][g][3] + brow1[f];
                *reinterpret_cast<float2*>(Yb + (size_t)row * HWn + col) = o0;
                *reinterpret_cast<float2*>(Yb + (size_t)(row + 8) * HWn + col) = o1;
                acc[f][g][0] = 0.f; acc[f][g][1] = 0.f;
                acc[f][g][2] = 0.f; acc[f][g][3] = 0.f;
            }
        }
    }
}

// ---------------- 3x3 depthwise stencil, 64-row tiles, cp.async staging -----
// Grid (2, 192, 24): yblock(64 rows), channel, tensor*8+b. 256 threads.
__global__ void __launch_bounds__(256) dwconv3(
    const float* __restrict__ dwq, const float* __restrict__ dbq,
    const float* __restrict__ dwk, const float* __restrict__ dbk,
    const float* __restrict__ dwv, const float* __restrict__ dbv)
{
    const int yb = blockIdx.x;
    const int c  = blockIdx.y;
    const int tz = blockIdx.z;
    const int tensor = tz >> 3, b = tz & 7;
    const int tid = threadIdx.x;

    const float* in  = (tensor == 0) ? g_tq : (tensor == 1) ? g_tk : g_tv;
    float*       out = (tensor == 0) ? g_q  : (tensor == 1) ? g_k  : g_v;
    const float* dw  = (tensor == 0) ? dwq  : (tensor == 1) ? dwk  : dwv;
    const float* db  = (tensor == 0) ? dbq  : (tensor == 1) ? dbk  : dbv;

    __shared__ __align__(16) float sm[66][136];
    __shared__ float red[8];

    const size_t chbase = ((size_t)b * Cn + c) * HWn;
    const int y0 = yb * 64;

    if (tid < 66) { sm[tid][3] = 0.0f; sm[tid][132] = 0.0f; }

    // stage rows y0-1 .. y0+64 (66 rows) via cp.async; OOB rows zero-filled
    #pragma unroll
    for (int i = tid; i < 66 * 32; i += 256) {
        const int r  = i >> 5;
        const int c4 = (i & 31) << 2;
        const int gy = y0 - 1 + r;
        if (gy >= 0 && gy < HIMG) {
            cp16(smem_u32(&sm[r][4 + c4]), in + chbase + (size_t)gy * WIMG + c4);
        } else {
            *reinterpret_cast<float4*>(&sm[r][4 + c4]) = make_float4(0.f, 0.f, 0.f, 0.f);
        }
    }
    CP_COMMIT();

    const float w0 = __ldg(dw + c * 9 + 0), w1 = __ldg(dw + c * 9 + 1), w2 = __ldg(dw + c * 9 + 2);
    const float w3 = __ldg(dw + c * 9 + 3), w4 = __ldg(dw + c * 9 + 4), w5 = __ldg(dw + c * 9 + 5);
    const float w6 = __ldg(dw + c * 9 + 6), w7 = __ldg(dw + c * 9 + 7), w8 = __ldg(dw + c * 9 + 8);
    const float bias = __ldg(db + c);
    CP_WAIT0();
    __syncthreads();

    // 256 threads: tid = half*128 + col; each covers 32 rows of its column
    const int t  = tid & 127;
    const int r0 = (tid >> 7) * 32;     // 0 or 32
    float a0 = sm[r0 + 0][t + 3], a1 = sm[r0 + 0][t + 4], a2 = sm[r0 + 0][t + 5];
    float b0 = sm[r0 + 1][t + 3], b1 = sm[r0 + 1][t + 4], b2 = sm[r0 + 1][t + 5];
    float nsum = 0.0f;
    #pragma unroll 8
    for (int r = 0; r < 32; r++) {
        const float d0 = sm[r0 + r + 2][t + 3], d1 = sm[r0 + r + 2][t + 4], d2 = sm[r0 + r + 2][t + 5];
        float o = bias;
        o = fmaf(w0, a0, o); o = fmaf(w1, a1, o); o = fmaf(w2, a2, o);
        o = fmaf(w3, b0, o); o = fmaf(w4, b1, o); o = fmaf(w5, b2, o);
        o = fmaf(w6, d0, o); o = fmaf(w7, d1, o); o = fmaf(w8, d2, o);
        out[chbase + (size_t)(y0 + r0 + r) * WIMG + t] = o;
        nsum = fmaf(o, o, nsum);
        a0 = b0; a1 = b1; a2 = b2;
        b0 = d0; b1 = d1; b2 = d2;
    }
    #pragma unroll
    for (int off = 16; off; off >>= 1) nsum += __shfl_xor_sync(0xffffffffu, nsum, off);
    if ((tid & 31) == 0) red[tid >> 5] = nsum;
    __syncthreads();
    if (tid == 0) {
        float s = 0.f;
        #pragma unroll
        for (int i = 0; i < 8; i++) s += red[i];
        g_npart[(((size_t)tensor * Bn + b) * Cn + c) * 2 + yb] = s;
    }
}

// ---------------- Gram partials: 128-px chunks, 6x6 tiles, cp.async loads ---
#define GSTR2 132
__global__ void __launch_bounds__(128) gram_stats()
{
    const int chunk = blockIdx.x;   // 0..127
    const int bh    = blockIdx.y;   // 0..63
    const int b = bh >> 3, h = bh & 7;
    const int tid = threadIdx.x;

    extern __shared__ float gsm[];
    float* qs = gsm;
    float* ks = gsm + 24 * GSTR2;
    float* vs = gsm + 48 * GSTR2;
    const uint32_t sq = smem_u32(qs);
    const uint32_t sk = smem_u32(ks);
    const uint32_t sv = smem_u32(vs);

    const int n0 = chunk * 128;
    for (int i = tid; i < 24 * 32; i += 128) {
        const int row = i >> 5;
        const int c4  = (i & 31) << 2;
        const size_t base = ((size_t)b * Cn + h * CPHn + row) * HWn + n0 + c4;
        const uint32_t off = (uint32_t)(row * GSTR2 + c4) * 4u;
        cp16(sq + off, g_q + base);
        cp16(sk + off, g_k + base);
        cp16(sv + off, g_v + base);
    }
    CP_COMMIT();
    CP_WAIT0();
    __syncthreads();

    const int g    = tid >> 6;
    const int t64  = tid & 63;
    const int kseg = t64 >> 4;
    const int t16  = t64 & 15;
    const int ci   = (t16 & 3) * 6;
    const int di   = (t16 >> 2) * 6;
    const float* Aa = g ? ks : qs;

    float acc[6][6];
    #pragma unroll
    for (int i = 0; i < 6; i++)
        #pragma unroll
        for (int j = 0; j < 6; j++) acc[i][j] = 0.0f;

    #pragma unroll 4
    for (int tk = 0; tk < 32; tk++) {
        const int k = kseg + (tk << 2);
        float a[6], vv[6];
        #pragma unroll
        for (int i = 0; i < 6; i++) a[i]  = Aa[(ci + i) * GSTR2 + k];
        #pragma unroll
        for (int j = 0; j < 6; j++) vv[j] = vs[(di + j) * GSTR2 + k];
        #pragma unroll
        for (int i = 0; i < 6; i++)
            #pragma unroll
            for (int j = 0; j < 6; j++)
                acc[i][j] = fmaf(a[i], vv[j], acc[i][j]);
    }
    __syncthreads();

    float* red = gsm;
    if (kseg > 0) {
        const int slot = ((g * 3 + (kseg - 1)) * 16 + t16) * 36;
        #pragma unroll
        for (int i = 0; i < 6; i++)
            #pragma unroll
            for (int j = 0; j < 6; j++)
                red[slot + i * 6 + j] = acc[i][j];
    }
    __syncthreads();
    if (kseg == 0) {
        #pragma unroll
        for (int s = 0; s < 3; s++) {
            const int slot = ((g * 3 + s) * 16 + t16) * 36;
            #pragma unroll
            for (int i = 0; i < 6; i++)
                #pragma unroll
                for (int j = 0; j < 6; j++)
                    acc[i][j] += red[slot + i * 6 + j];
        }
        float* dst = g_gpart + (((size_t)bh * 2 + g) * 128 + chunk) * 576;
        #pragma unroll
        for (int i = 0; i < 6; i++)
            #pragma unroll
            for (int j = 0; j < 6; j++)
                dst[(ci + i) * 24 + (di + j)] = acc[i][j];
    }
}

// ---------------- reduce Gram partials (deterministic) ----------------------
__global__ void __launch_bounds__(256) reduce_stats()
{
    const int idx = blockIdx.x * 256 + threadIdx.x;
    if (idx < 64 * 2 * 576) {
        const int e = idx % 576;
        const int r = idx / 576;
        float s = 0.0f;
        const float* src = g_gpart + (size_t)r * 128 * 576 + e;
        #pragma unroll 8
        for (int t = 0; t < 128; t++) s += src[(size_t)t * 576];
        g_S[idx] = s;
    }
}

// ---------------- softmax + attn1@attn2 + W_proj fold -> A[b] bf16 ----------
__global__ void __launch_bounds__(192) attn_fold(
    const float* __restrict__ temp, const float* __restrict__ wp)
{
    const int bh = blockIdx.x;
    const int b = bh >> 3, h = bh & 7;
    const int tidx = threadIdx.x;
    const int lane = tidx & 31;
    __shared__ float a1[24][25], a2[24][25];
    __shared__ float Msh[24][25];
    __shared__ float nrm[3][24];

    if (tidx < 32) {
        if (lane < 24) {
            const int c = h * CPHn + lane;
            #pragma unroll
            for (int tz = 0; tz < 3; tz++) {
                const float* p = g_npart + (((size_t)tz * Bn + b) * Cn + c) * 2;
                nrm[tz][lane] = fmaxf(sqrtf(p[0] + p[1]), 1e-12f);
            }
        }
        __syncwarp();
        const float tp = temp[h];
        if (lane < 24) {
            const float* S1 = g_S + (bh * 2 + 0) * 576 + lane * 24;
            const float* S2 = g_S + (bh * 2 + 1) * 576 + lane * 24;
            const float iq = tp / nrm[0][lane];
            const float ik = tp / nrm[1][lane];
            float r1[24], r2[24];
            float m1 = -1e30f, m2 = -1e30f;
            #pragma unroll
            for (int d = 0; d < 24; d++) {
                const float iv = 1.0f / nrm[2][d];
                r1[d] = S1[d] * iq * iv;
                r2[d] = S2[d] * ik * iv;
                m1 = fmaxf(m1, r1[d]);
                m2 = fmaxf(m2, r2[d]);
            }
            float s1 = 0.f, s2 = 0.f;
            #pragma unroll
            for (int d = 0; d < 24; d++) {
                r1[d] = expf(r1[d] - m1); s1 += r1[d];
                r2[d] = expf(r2[d] - m2); s2 += r2[d];
            }
            const float i1 = 1.0f / s1, i2 = 1.0f / s2;
            #pragma unroll
            for (int d = 0; d < 24; d++) {
                a1[lane][d] = r1[d] * i1;
                a2[lane][d] = r2[d] * i2;
            }
        }
        __syncwarp();
        if (lane < 24) {
            #pragma unroll
            for (int d = 0; d < 24; d++) {
                float s = 0.f;
                #pragma unroll
                for (int e = 0; e < 24; e++) s = fmaf(a1[lane][e], a2[e][d], s);
                Msh[lane][d] = s / nrm[2][d];
            }
        }
    }
    __syncthreads();

    const int o = tidx;   // 0..191
    const float* wrow = wp + (size_t)o * Cn + h * CPHn;
    float wreg[24];
    #pragma unroll
    for (int c2 = 0; c2 < CPHn; c2++) wreg[c2] = __ldg(wrow + c2);
    const size_t base = (size_t)(3 + b) * Cn * Cn + (size_t)o * Cn + h * CPHn;
    #pragma unroll
    for (int d = 0; d < CPHn; d++) {
        float s = 0.f;
        #pragma unroll
        for (int c2 = 0; c2 < CPHn; c2++) s = fmaf(wreg[c2], Msh[c2][d], s);
        __nv_bfloat16 hi = __float2bfloat16(s);
        __nv_bfloat16 lo = __float2bfloat16(s - __bfloat162float(hi));
        g_Whi[base + d] = hi;
        g_Wlo[base + d] = lo;
    }
}

// ---------------- launch ----------------------------------------------------
extern "C" void kernel_launch(void* const* d_in, const int* in_sizes, int n_in,
                              void* d_out, int out_size)
{
    const float* x    = (const float*)d_in[0];
    const float* edge = (const float*)d_in[1];
    const float* grad = (const float*)d_in[2];
    const float* w_q  = (const float*)d_in[3];  const float* b_q  = (const float*)d_in[4];
    const float* w_k  = (const float*)d_in[5];  const float* b_k  = (const float*)d_in[6];
    const float* w_v  = (const float*)d_in[7];  const float* b_v  = (const float*)d_in[8];
    const float* dw_q = (const float*)d_in[9];  const float* db_q = (const float*)d_in[10];
    const float* dw_k = (const float*)d_in[11]; const float* db_k = (const float*)d_in[12];
    const float* dw_v = (const float*)d_in[13]; const float* db_v = (const float*)d_in[14];
    const float* w_p  = (const float*)d_in[15]; const float* b_p  = (const float*)d_in[16];
    const float* temp = (const float*)d_in[17];
    float* out = (float*)d_out;

    float *tq, *tk, *tv, *vv;
    cudaGetSymbolAddress((void**)&tq,  g_tq);
    cudaGetSymbolAddress((void**)&tk,  g_tk);
    cudaGetSymbolAddress((void**)&tv,  g_tv);
    cudaGetSymbolAddress((void**)&vv,  g_v);

    cudaFuncSetAttribute((const void*)gemm_mma,
                         cudaFuncAttributeMaxDynamicSharedMemorySize, SMEM_MMA);
    const int gsmem = 3 * 24 * GSTR2 * (int)sizeof(float);   // 38016
    cudaFuncSetAttribute((const void*)gram_stats,
                         cudaFuncAttributeMaxDynamicSharedMemorySize, gsmem);

    cvt_weights<<<3, 256>>>(w_q, w_k, w_v);
    // merged q/k/v conv1x1 GEMMs
    gemm_mma<<<148, 256, SMEM_MMA>>>(0, edge, grad, x, tq, tk, tv, b_q, b_k, b_v);
    dwconv3<<<dim3(2, 192, 24), 256>>>(dw_q, db_q, dw_k, db_k, dw_v, db_v);
    gram_stats<<<dim3(128, 64), 128, gsmem>>>();
    reduce_stats<<<288, 256>>>();
    attn_fold<<<64, 192>>>(temp, w_p);
    // final GEMM: out = A[b] @ v + b_proj
    gemm_mma<<<148, 256, SMEM_MMA>>>(1, vv, nullptr, nullptr, out, nullptr, nullptr,
                                     b_p, nullptr, nullptr);
}